// round 13
// baseline (speedup 1.0000x reference)
#include <cuda_runtime.h>
#include <cuda_fp16.h>
#include <cstdint>
#include <cstddef>

// Problem dims (fixed)
#define NROWS 4096
#define MCOLS 4096
#define DDIM  1024
#define E_SCALE 256.0f

// ---------------------------------------------------------------------------
// Scratch (__device__ globals — allocation-free contract)
// ---------------------------------------------------------------------------
__device__ __half g_Hh[(size_t)NROWS * DDIM];     // H * (1/32) in fp16
__device__ __half g_Kh[(size_t)MCOLS * DDIM];     // K in fp16
__device__ __half g_Vt[(size_t)DDIM * MCOLS];     // V^T in fp16 (K-major)
__device__ __half g_expsc[(size_t)NROWS * MCOLS]; // exp(scores) fp16
__device__ __half g_e[(size_t)NROWS * MCOLS];     // expm1(p*mask)*256 fp16
__device__ float g_z[NROWS];
__device__ float g_part[(size_t)NROWS * 64];   // GEMM1 row-sum partials [row][slot]
__device__ float g_partc[128 * DDIM];          // V colsum partials (128 row-tiles)

static __device__ __forceinline__ uint32_t smem_u32(const void* p) {
    uint32_t a;
    asm("{ .reg .u64 t; cvta.to.shared.u64 t, %1; cvt.u32.u64 %0, t; }"
        : "=r"(a) : "l"(p));
    return a;
}

static __device__ __forceinline__ uint32_t sw128(uint32_t off) {
    return off ^ ((off >> 3) & 0x70);
}

static __device__ __forceinline__ void cp16(uint32_t saddr, const void* gptr) {
    asm volatile("cp.async.cg.shared.global [%0], [%1], 16;"
                 :: "r"(saddr), "l"(gptr));
}

static __device__ __forceinline__ void cp_commit() {
    asm volatile("cp.async.commit_group;");
}

template <int N>
static __device__ __forceinline__ void cp_wait() {
    asm volatile("cp.async.wait_group %0;" :: "n"(N));
}

static __device__ __forceinline__ void ldmatrix_x4(uint32_t* r, uint32_t saddr) {
    asm volatile("ldmatrix.sync.aligned.m8n8.x4.shared.b16 {%0,%1,%2,%3}, [%4];"
                 : "=r"(r[0]), "=r"(r[1]), "=r"(r[2]), "=r"(r[3]) : "r"(saddr));
}

// fp16-accumulate HMMA (numerics validated: rel_err 8.7e-7 end-to-end)
static __device__ __forceinline__ void mma_h(uint32_t* d, const uint32_t* a,
                                             const uint32_t* b) {
    asm volatile(
        "mma.sync.aligned.m16n8k16.row.col.f16.f16.f16.f16 "
        "{%0,%1}, {%2,%3,%4,%5}, {%6,%7}, {%0,%1};"
        : "+r"(d[0]), "+r"(d[1])
        : "r"(a[0]), "r"(a[1]), "r"(a[2]), "r"(a[3]), "r"(b[0]), "r"(b[1]));
}

// ===========================================================================
// GEMM1: fp16 mma, 128(M) x 256(N) CTA tile, BK=64, 256 thr (8 warps 2x4,
//   warp tile 64x64), ST=2 double buffer, 2 CTAs/SM ping-pong.
//   Pipeline: wait ALL (group for buffer `it` fully resident) -> sync ->
//   prefetch it+1 into other buffer (overlaps compute of it).
//   epilogue: expsc = fp16(exp(acc)); deterministic row-sum partials
// ===========================================================================
#define BM1 128
#define BN1 256
#define BK1 64
#define TPB1 256
#define A1_BYTES 16384             // 128 x 64 fp16
#define B1_BYTES 32768             // 256 x 64 fp16
#define STG1_BYTES (A1_BYTES + B1_BYTES)
#define SMEM1_BYTES (2 * STG1_BYTES)   // 96 KB -> 2 CTAs/SM

static __device__ __forceinline__ void issue_stage1(
    const __half* __restrict__ A, const __half* __restrict__ B,
    int rowBase, int colBase, int k0, uint32_t sbase, int tid) {
    uint32_t sA = sbase;
    uint32_t sB = sbase + A1_BYTES;
#pragma unroll
    for (int i = 0; i < 4; i++) {      // A: 1024 chunks
        int l = tid + i * TPB1;
        int r = l >> 3, c = l & 7;
        uint32_t off = sw128((uint32_t)(r * 128 + c * 16));
        cp16(sA + off, A + (size_t)(rowBase + r) * DDIM + k0 + c * 8);
    }
#pragma unroll
    for (int i = 0; i < 8; i++) {      // B: 2048 chunks
        int l = tid + i * TPB1;
        int r = l >> 3, c = l & 7;
        uint32_t off = sw128((uint32_t)(r * 128 + c * 16));
        cp16(sB + off, B + (size_t)(colBase + r) * DDIM + k0 + c * 8);
    }
}

__global__ void __launch_bounds__(TPB1, 2)
gemm1_h(const __half* __restrict__ A, const __half* __restrict__ B,
        __half* __restrict__ Cb, float* __restrict__ part) {
    extern __shared__ __align__(1024) char smem[];
    uint32_t sb = smem_u32(smem);
    int tid = threadIdx.x;
    int wid = tid >> 5, lane = tid & 31;
    int wm = wid >> 2, wn = wid & 3;        // 2x4 warp grid, warp = 64m x 64n
    int rowBase = blockIdx.y * BM1;
    int colBase = blockIdx.x * BN1;
    const int nIter = DDIM / BK1;           // 16

    issue_stage1(A, B, rowBase, colBase, 0, sb, tid);
    cp_commit();

    uint32_t acc[4][8][2];
#pragma unroll
    for (int i = 0; i < 4; i++)
#pragma unroll
        for (int j = 0; j < 8; j++) { acc[i][j][0] = 0u; acc[i][j][1] = 0u; }

    int arow = wm * 64 + (lane & 15);
    int acolb = (lane >> 4) << 4;
    int brow = wn * 64 + ((lane >> 4) << 3) + (lane & 7);
    int bcolb = ((lane >> 3) & 1) << 4;

    for (int it = 0; it < nIter; ++it) {
        cp_wait<0>();      // buffer `it` fully resident (FIX: was wait<1> = NaN)
        __syncthreads();   // + all warps done computing it-1 -> other buf free
        if (it + 1 < nIter) {
            issue_stage1(A, B, rowBase, colBase, (it + 1) * BK1,
                         sb + ((it + 1) & 1) * STG1_BYTES, tid);
            cp_commit();   // loads overlap the MMA work below
        }

        uint32_t baseA = sb + (it & 1) * STG1_BYTES;
        uint32_t baseB = baseA + A1_BYTES;
#pragma unroll
        for (int ks = 0; ks < 4; ks++) {
            uint32_t af[4][4];
#pragma unroll
            for (int mi = 0; mi < 4; mi++) {
                uint32_t off = sw128((uint32_t)((arow + mi * 16) * 128 + ks * 32 + acolb));
                ldmatrix_x4(af[mi], baseA + off);
            }
            uint32_t bf[4][4];
#pragma unroll
            for (int ni = 0; ni < 4; ni++) {
                uint32_t off = sw128((uint32_t)((brow + ni * 16) * 128 + ks * 32 + bcolb));
                ldmatrix_x4(bf[ni], baseB + off);
            }
#pragma unroll
            for (int mi = 0; mi < 4; mi++)
#pragma unroll
                for (int ni = 0; ni < 4; ni++) {
                    mma_h(acc[mi][2 * ni], af[mi], &bf[ni][0]);
                    mma_h(acc[mi][2 * ni + 1], af[mi], &bf[ni][2]);
                }
        }
    }

    int mrow = rowBase + wm * 64 + (lane >> 2);
    int ncol = colBase + wn * 64 + 2 * (lane & 3);

#pragma unroll
    for (int mi = 0; mi < 4; mi++) {
        int m0 = mrow + mi * 16;
        float s0 = 0.f, s1 = 0.f;
#pragma unroll
        for (int nj = 0; nj < 8; nj++) {
            int n = ncol + nj * 8;
            float2 r0 = __half22float2(*reinterpret_cast<__half2*>(&acc[mi][nj][0]));
            float2 r1 = __half22float2(*reinterpret_cast<__half2*>(&acc[mi][nj][1]));
            float e00 = __expf(r0.x);
            float e01 = __expf(r0.y);
            float e10 = __expf(r1.x);
            float e11 = __expf(r1.y);
            s0 += e00 + e01;
            s1 += e10 + e11;
            *reinterpret_cast<__half2*>(Cb + (size_t)m0 * MCOLS + n) =
                __floats2half2_rn(e00, e01);
            *reinterpret_cast<__half2*>(Cb + (size_t)(m0 + 8) * MCOLS + n) =
                __floats2half2_rn(e10, e11);
        }
        // fixed-order lane reduce (4 lanes share each row)
        s0 += __shfl_xor_sync(0xffffffffu, s0, 1);
        s0 += __shfl_xor_sync(0xffffffffu, s0, 2);
        s1 += __shfl_xor_sync(0xffffffffu, s1, 1);
        s1 += __shfl_xor_sync(0xffffffffu, s1, 2);
        if ((lane & 3) == 0) {
            int slot = blockIdx.x * 4 + wn;       // 16 coltiles x 4 warps = 64
            part[(size_t)m0 * 64 + slot]       = s0;
            part[(size_t)(m0 + 8) * 64 + slot] = s1;
        }
    }
}

// ===========================================================================
// GEMM2: fp16 mma, 128(M) x 128(N) CTA tile, BK=64, 256 thr (8 warps 2x4,
//   warp tile 64x32), ST=3, 2 CTAs/SM. out = (Scol[col] + acc/256)/Zrow[row]
//   (3-deep pipeline: wait<1> drains exactly the oldest/consumed buffer.)
// ===========================================================================
#define BM2 128
#define BN2 128
#define BK2 64
#define TPB2 256
#define ST2 3
#define A2_BYTES 16384             // 128 x 64 fp16
#define B2_BYTES 16384             // 128 x 64 fp16
#define STG2_BYTES (A2_BYTES + B2_BYTES)
#define SMEM2_BYTES (ST2 * STG2_BYTES)   // 96 KB -> 2 CTAs/SM

static __device__ __forceinline__ void issue_stage2(
    const __half* __restrict__ A, const __half* __restrict__ B,
    int rowBase, int colBase, int k0, uint32_t sbase, int tid) {
    uint32_t sA = sbase;
    uint32_t sB = sbase + A2_BYTES;
#pragma unroll
    for (int i = 0; i < 4; i++) {      // A, B: 1024 chunks each
        int l = tid + i * TPB2;
        int r = l >> 3, c = l & 7;
        uint32_t off = sw128((uint32_t)(r * 128 + c * 16));
        cp16(sA + off, A + (size_t)(rowBase + r) * MCOLS + k0 + c * 8);
        cp16(sB + off, B + (size_t)(colBase + r) * MCOLS + k0 + c * 8);
    }
}

__global__ void __launch_bounds__(TPB2, 2)
gemm2_h(const __half* __restrict__ A, const __half* __restrict__ B,
        float* __restrict__ C,
        const float* __restrict__ ScolPart, const float* __restrict__ Zrow) {
    extern __shared__ __align__(1024) char smem[];
    uint32_t sb = smem_u32(smem);
    int tid = threadIdx.x;
    int wid = tid >> 5, lane = tid & 31;
    int wm = wid >> 2, wn = wid & 3;        // 2x4 warp grid, warp = 64m x 32n
    int rowBase = blockIdx.y * BM2;
    int colBase = blockIdx.x * BN2;
    const int nIter = MCOLS / BK2;          // 64

#pragma unroll
    for (int s = 0; s < ST2 - 1; s++) {
        issue_stage2(A, B, rowBase, colBase, s * BK2, sb + s * STG2_BYTES, tid);
        cp_commit();
    }

    uint32_t acc[4][4][2];
#pragma unroll
    for (int i = 0; i < 4; i++)
#pragma unroll
        for (int j = 0; j < 4; j++) { acc[i][j][0] = 0u; acc[i][j][1] = 0u; }

    int arow = wm * 64 + (lane & 15);
    int acolb = (lane >> 4) << 4;
    int brow = wn * 32 + ((lane >> 4) << 3) + (lane & 7);
    int bcolb = ((lane >> 3) & 1) << 4;

    for (int it = 0; it < nIter; ++it) {
        cp_wait<1>();      // oldest pending = group for buffer `it` -> drained
        __syncthreads();   // all warps done computing it-1 -> its buffer free
        if (it + ST2 - 1 < nIter) {
            issue_stage2(A, B, rowBase, colBase, (it + ST2 - 1) * BK2,
                         sb + (((it + ST2 - 1) % ST2) * STG2_BYTES), tid);
            cp_commit();
        }

        uint32_t baseA = sb + (it % ST2) * STG2_BYTES;
        uint32_t baseB = baseA + A2_BYTES;
#pragma unroll
        for (int ks = 0; ks < 4; ks++) {
            uint32_t af[4][4];
#pragma unroll
            for (int mi = 0; mi < 4; mi++) {
                uint32_t off = sw128((uint32_t)((arow + mi * 16) * 128 + ks * 32 + acolb));
                ldmatrix_x4(af[mi], baseA + off);
            }
            uint32_t bf[2][4];
#pragma unroll
            for (int ni = 0; ni < 2; ni++) {
                uint32_t off = sw128((uint32_t)((brow + ni * 16) * 128 + ks * 32 + bcolb));
                ldmatrix_x4(bf[ni], baseB + off);
            }
#pragma unroll
            for (int mi = 0; mi < 4; mi++)
#pragma unroll
                for (int ni = 0; ni < 2; ni++) {
                    mma_h(acc[mi][2 * ni], af[mi], &bf[ni][0]);
                    mma_h(acc[mi][2 * ni + 1], af[mi], &bf[ni][2]);
                }
        }
    }

    // Scol reduction into smem (safe: all cp.async drained)
    cp_wait<0>();
    __syncthreads();
    float* sS = reinterpret_cast<float*>(smem);
    if (tid < BN2) {
        float s0 = 0.f, s1 = 0.f, s2 = 0.f, s3 = 0.f;
        const float* p = ScolPart + colBase + tid;
#pragma unroll
        for (int i = 0; i < 128; i += 4) {
            s0 += p[(size_t)i * DDIM];
            s1 += p[(size_t)(i + 1) * DDIM];
            s2 += p[(size_t)(i + 2) * DDIM];
            s3 += p[(size_t)(i + 3) * DDIM];
        }
        sS[tid] = (s0 + s1) + (s2 + s3);
    }
    __syncthreads();

    const float invE = 1.0f / E_SCALE;
    int mrow = rowBase + wm * 64 + (lane >> 2);
    int ncol = colBase + wn * 32 + 2 * (lane & 3);
#pragma unroll
    for (int mi = 0; mi < 4; mi++) {
        int m0 = mrow + mi * 16;
        float rz0 = 1.0f / Zrow[m0];
        float rz1 = 1.0f / Zrow[m0 + 8];
#pragma unroll
        for (int nj = 0; nj < 4; nj++) {
            int n = ncol + nj * 8;
            float s0 = sS[n - colBase], s1 = sS[n - colBase + 1];
            float2 r0 = __half22float2(*reinterpret_cast<__half2*>(&acc[mi][nj][0]));
            float2 r1 = __half22float2(*reinterpret_cast<__half2*>(&acc[mi][nj][1]));
            float2 v0, v1;
            v0.x = (s0 + r0.x * invE) * rz0;
            v0.y = (s1 + r0.y * invE) * rz0;
            v1.x = (s0 + r1.x * invE) * rz1;
            v1.y = (s1 + r1.y * invE) * rz1;
            *reinterpret_cast<float2*>(C + (size_t)m0 * DDIM + n) = v0;
            *reinterpret_cast<float2*>(C + (size_t)(m0 + 8) * DDIM + n) = v1;
        }
    }
}

// ---------------------------------------------------------------------------
// Elementwise / reduction kernels
// ---------------------------------------------------------------------------
// fp32 -> fp16 with scale; each thread: 2 x float4 loads, 1 x 16B store
__global__ void conv_f2h(const float* __restrict__ src, __half* __restrict__ dst,
                         float scale) {
    int i = blockIdx.x * blockDim.x + threadIdx.x;   // 8-element group id
    const float4* s4 = reinterpret_cast<const float4*>(src) + 2 * (size_t)i;
    float4 a = s4[0], b = s4[1];
    __half2 h[4];
    h[0] = __floats2half2_rn(a.x * scale, a.y * scale);
    h[1] = __floats2half2_rn(a.z * scale, a.w * scale);
    h[2] = __floats2half2_rn(b.x * scale, b.y * scale);
    h[3] = __floats2half2_rn(b.z * scale, b.w * scale);
    reinterpret_cast<uint4*>(dst)[i] = *reinterpret_cast<uint4*>(h);
}

// V^T (fp16) + per-row-tile column partial sums (single pass over V)
__global__ void transposeV(const float* __restrict__ V, __half* __restrict__ Vt,
                           float* __restrict__ partc) {
    __shared__ float tile[32][33];
    __shared__ float red[8][32];
    int d0 = blockIdx.x * 32, m0 = blockIdx.y * 32;
    int tx = threadIdx.x, ty = threadIdx.y;  // 32 x 8
#pragma unroll
    for (int j = 0; j < 32; j += 8)
        tile[ty + j][tx] = V[(size_t)(m0 + ty + j) * DDIM + d0 + tx];
    __syncthreads();
    // fp16 transpose: thread handles (d_local = ty*4 + tx/8, m = 4*(tx&7)..+3)
    {
        int dl = ty * 4 + (tx >> 3);
        int ml = 4 * (tx & 7);
        __half2 w0 = __floats2half2_rn(tile[ml][dl], tile[ml + 1][dl]);
        __half2 w1 = __floats2half2_rn(tile[ml + 2][dl], tile[ml + 3][dl]);
        __half2* dst = reinterpret_cast<__half2*>(Vt + (size_t)(d0 + dl) * MCOLS + m0 + ml);
        dst[0] = w0;
        dst[1] = w1;
    }
    // column partials: sum over the 32 m-rows for each d = tx
    float s = (tile[ty * 4 + 0][tx] + tile[ty * 4 + 1][tx]) +
              (tile[ty * 4 + 2][tx] + tile[ty * 4 + 3][tx]);
    red[ty][tx] = s;
    __syncthreads();
    if (ty == 0) {
        float t = 0.f;
#pragma unroll
        for (int i = 0; i < 8; i++) t += red[i][tx];
        partc[(size_t)blockIdx.y * DDIM + d0 + tx] = t;
    }
}

static __device__ __forceinline__ float warp_red_sum(float v) {
#pragma unroll
    for (int o = 16; o > 0; o >>= 1) v += __shfl_xor_sync(0xffffffffu, v, o);
    return v;
}

// fast expm1 for small non-negative x: cubic Taylor, guard to expm1f
static __device__ __forceinline__ float expm1_fast(float x) {
    float p = x * (1.0f + x * (0.5f + x * 0.16666667f));
    return (x > 0.0625f) ? expm1f(x) : p;
}

// build_e with fused row-sum reduction (reads 64 partials in-block)
__global__ void build_e(const __half* __restrict__ expsc,
                        const float* __restrict__ mask,
                        const float* __restrict__ part,
                        __half* __restrict__ e, float* __restrict__ zrow) {
    __shared__ float red[8];
    __shared__ float srsum;
    int n = blockIdx.x, t = threadIdx.x;
    int wid = t >> 5, lid = t & 31;
    // warp 0: reduce the 64 row partials (fixed order)
    if (wid == 0) {
        const float* p = part + (size_t)n * 64;
        float s = p[lid] + p[lid + 32];
        s = warp_red_sum(s);
        if (lid == 0) srsum = s;
    }
    const __half2* srow = reinterpret_cast<const __half2*>(expsc + (size_t)n * MCOLS);
    const float4* mrow = reinterpret_cast<const float4*>(mask + (size_t)n * MCOLS);
    __half2* erow = reinterpret_cast<__half2*>(e + (size_t)n * MCOLS);
    __syncthreads();
    float inv = 1.0f / srsum;
    float z = 0.f;
#pragma unroll
    for (int i = 0; i < 4; i++) {
        int idx = t + i * 256;
        float4 m = mrow[idx];
        __half2 p0 = srow[2 * idx];
        __half2 p1 = srow[2 * idx + 1];
        float e0 = expm1_fast(__low2float(p0)  * inv * m.x);
        float e1 = expm1_fast(__high2float(p0) * inv * m.y);
        float e2 = expm1_fast(__low2float(p1)  * inv * m.z);
        float e3 = expm1_fast(__high2float(p1) * inv * m.w);
        z += (e0 + e1) + (e2 + e3);
        erow[2 * idx]     = __floats2half2_rn(e0 * E_SCALE, e1 * E_SCALE);
        erow[2 * idx + 1] = __floats2half2_rn(e2 * E_SCALE, e3 * E_SCALE);
    }
    z = warp_red_sum(z);
    if (lid == 0) red[wid] = z;
    __syncthreads();
    if (t == 0) {
        float acc = 0.f;
#pragma unroll
        for (int i = 0; i < 8; i++) acc += red[i];
        zrow[n] = (float)MCOLS + acc;
    }
}

// ---------------------------------------------------------------------------
// Launch
// ---------------------------------------------------------------------------
extern "C" void kernel_launch(void* const* d_in, const int* in_sizes, int n_in,
                              void* d_out, int out_size) {
    const float* H   = (const float*)d_in[0];
    const float* K   = (const float*)d_in[1];
    const float* V   = (const float*)d_in[2];
    const float* Msk = (const float*)d_in[3];
    float* out = (float*)d_out;

    void *hh, *kh, *vt, *es, *ee, *zz, *part, *partc;
    cudaGetSymbolAddress(&hh, g_Hh);
    cudaGetSymbolAddress(&kh, g_Kh);
    cudaGetSymbolAddress(&vt, g_Vt);
    cudaGetSymbolAddress(&es, g_expsc);
    cudaGetSymbolAddress(&ee, g_e);
    cudaGetSymbolAddress(&zz, g_z);
    cudaGetSymbolAddress(&part, g_part);
    cudaGetSymbolAddress(&partc, g_partc);

    cudaFuncSetAttribute(gemm1_h, cudaFuncAttributeMaxDynamicSharedMemorySize,
                         SMEM1_BYTES);
    cudaFuncSetAttribute(gemm2_h, cudaFuncAttributeMaxDynamicSharedMemorySize,
                         SMEM2_BYTES);

    // Launch order keeps gemm1_h at slot 4 (the ncu-profiled slot).
    conv_f2h<<<(NROWS * DDIM / 8) / 256, 256>>>(H, (__half*)hh, 1.0f / 32.0f);  // 1
    conv_f2h<<<(MCOLS * DDIM / 8) / 256, 256>>>(K, (__half*)kh, 1.0f);          // 2
    transposeV<<<dim3(DDIM / 32, MCOLS / 32), dim3(32, 8)>>>(V, (__half*)vt,
                                                             (float*)partc);    // 3

    // Stage 1: expsc = fp16(exp(H/32 @ K^T)) + row-sum partials (fused epilogue)
    gemm1_h<<<dim3(MCOLS / BN1, NROWS / BM1), TPB1, SMEM1_BYTES>>>(
        (const __half*)hh, (const __half*)kh, (__half*)es, (float*)part);       // 4

    // Stage 2: e = fp16(expm1(softmax1 * mask) * 256); z = M + sum(e)
    build_e<<<NROWS, 256>>>((const __half*)es, Msk, (const float*)part,
                            (__half*)ee, (float*)zz);                           // 5

    // Stage 3: out = (colsum(V) + (e @ V)/256) / z   (fp16-acc tensor cores)
    gemm2_h<<<dim3(DDIM / BN2, NROWS / BM2), TPB2, SMEM2_BYTES>>>(
        (const __half*)ee, (const __half*)vt, out,
        (const float*)partc, (const float*)zz);                                 // 6
}

// round 14
// speedup vs baseline: 1.0017x; 1.0017x over previous
#include <cuda_runtime.h>
#include <cuda_fp16.h>
#include <cstdint>
#include <cstddef>

// Problem dims (fixed)
#define NROWS 4096
#define MCOLS 4096
#define DDIM  1024
#define E_SCALE 256.0f

// ---------------------------------------------------------------------------
// Scratch (__device__ globals — allocation-free contract)
// ---------------------------------------------------------------------------
__device__ __half g_Hh[(size_t)NROWS * DDIM];     // H * (1/32) in fp16
__device__ __half g_Kh[(size_t)MCOLS * DDIM];     // K in fp16
__device__ __half g_Vt[(size_t)DDIM * MCOLS];     // V^T in fp16 (K-major)
__device__ __half g_expsc[(size_t)NROWS * MCOLS]; // exp(scores) fp16
__device__ __half g_e[(size_t)NROWS * MCOLS];     // expm1(p*mask)*256 fp16
__device__ float g_z[NROWS];
__device__ float g_part[(size_t)NROWS * 128];  // GEMM1 row-sum partials [row][slot]
__device__ float g_partc[128 * DDIM];          // V colsum partials (128 row-tiles)

static __device__ __forceinline__ uint32_t smem_u32(const void* p) {
    uint32_t a;
    asm("{ .reg .u64 t; cvta.to.shared.u64 t, %1; cvt.u32.u64 %0, t; }"
        : "=r"(a) : "l"(p));
    return a;
}

static __device__ __forceinline__ uint32_t sw128(uint32_t off) {
    return off ^ ((off >> 3) & 0x70);
}

static __device__ __forceinline__ void cp16(uint32_t saddr, const void* gptr) {
    asm volatile("cp.async.cg.shared.global [%0], [%1], 16;"
                 :: "r"(saddr), "l"(gptr));
}

static __device__ __forceinline__ void cp_commit() {
    asm volatile("cp.async.commit_group;");
}

template <int N>
static __device__ __forceinline__ void cp_wait() {
    asm volatile("cp.async.wait_group %0;" :: "n"(N));
}

static __device__ __forceinline__ void ldmatrix_x4(uint32_t* r, uint32_t saddr) {
    asm volatile("ldmatrix.sync.aligned.m8n8.x4.shared.b16 {%0,%1,%2,%3}, [%4];"
                 : "=r"(r[0]), "=r"(r[1]), "=r"(r[2]), "=r"(r[3]) : "r"(saddr));
}

// fp16-accumulate HMMA (numerics validated: rel_err 8.7e-7 end-to-end)
static __device__ __forceinline__ void mma_h(uint32_t* d, const uint32_t* a,
                                             const uint32_t* b) {
    asm volatile(
        "mma.sync.aligned.m16n8k16.row.col.f16.f16.f16.f16 "
        "{%0,%1}, {%2,%3,%4,%5}, {%6,%7}, {%0,%1};"
        : "+r"(d[0]), "+r"(d[1])
        : "r"(a[0]), "r"(a[1]), "r"(a[2]), "r"(a[3]), "r"(b[0]), "r"(b[1]));
}

// ===========================================================================
// Shared GEMM geometry: 128x128 CTA tile, BK=64, 256 thr, 8 warps (2x4),
//   warp tile 64x32, ST=3 (96 KB -> 2 CTAs/SM), fragment double-buffering:
//   ks+1 LDSM issued BEFORE ks MMAs (hides LDS latency under tensor work).
// ===========================================================================
#define BMX 128
#define BNX 128
#define BKX 64
#define TPBX 256
#define STX 3
#define AX_BYTES 16384             // 128 x 64 fp16
#define STGX_BYTES (2 * AX_BYTES)
#define SMEMX_BYTES (STX * STGX_BYTES)   // 96 KB

static __device__ __forceinline__ void issue_stageX(
    const __half* __restrict__ A, const __half* __restrict__ B,
    int lda, int rowBase, int colBase, int k0, uint32_t sbase, int tid) {
    uint32_t sA = sbase;
    uint32_t sB = sbase + AX_BYTES;
#pragma unroll
    for (int i = 0; i < 4; i++) {      // A, B: 1024 x 16B chunks each
        int l = tid + i * TPBX;
        int r = l >> 3, c = l & 7;
        uint32_t off = sw128((uint32_t)(r * 128 + c * 16));
        cp16(sA + off, A + (size_t)(rowBase + r) * lda + k0 + c * 8);
        cp16(sB + off, B + (size_t)(colBase + r) * lda + k0 + c * 8);
    }
}

// Mainloop macro-body shared by both kernels via an inline function.
// Computes acc[4][4][2] (64m x 32n per warp) over nIter BK=64 chunks.
static __device__ __forceinline__ void gemm_mainloop(
    const __half* __restrict__ A, const __half* __restrict__ B, int lda,
    int rowBase, int colBase, int nIter, uint32_t sb, int tid,
    int arow, int acolb, int brow, int bcolb, uint32_t acc[4][4][2]) {

#pragma unroll
    for (int s = 0; s < STX - 1; s++) {
        issue_stageX(A, B, lda, rowBase, colBase, s * BKX,
                     sb + s * STGX_BYTES, tid);
        cp_commit();
    }

    for (int it = 0; it < nIter; ++it) {
        cp_wait<1>();      // oldest pending group = buffer `it` -> resident
        __syncthreads();   // all warps done with buffer (it+STX-1)%STX
        if (it + STX - 1 < nIter) {
            issue_stageX(A, B, lda, rowBase, colBase, (it + STX - 1) * BKX,
                         sb + ((it + STX - 1) % STX) * STGX_BYTES, tid);
            cp_commit();
        }

        uint32_t baseA = sb + (it % STX) * STGX_BYTES;
        uint32_t baseB = baseA + AX_BYTES;

        uint32_t af[2][16], bf[2][8];
        // preload ks=0 fragments
#pragma unroll
        for (int mi = 0; mi < 4; mi++)
            ldmatrix_x4(&af[0][mi * 4],
                        baseA + sw128((uint32_t)((arow + mi * 16) * 128 + acolb)));
#pragma unroll
        for (int ni = 0; ni < 2; ni++)
            ldmatrix_x4(&bf[0][ni * 4],
                        baseB + sw128((uint32_t)((brow + ni * 16) * 128 + bcolb)));

#pragma unroll
        for (int ks = 0; ks < 4; ks++) {
            int cur = ks & 1, nxt = cur ^ 1;
            if (ks < 3) {   // prefetch ks+1 fragments BEFORE consuming ks
#pragma unroll
                for (int mi = 0; mi < 4; mi++)
                    ldmatrix_x4(&af[nxt][mi * 4],
                                baseA + sw128((uint32_t)((arow + mi * 16) * 128 +
                                                         (ks + 1) * 32 + acolb)));
#pragma unroll
                for (int ni = 0; ni < 2; ni++)
                    ldmatrix_x4(&bf[nxt][ni * 4],
                                baseB + sw128((uint32_t)((brow + ni * 16) * 128 +
                                                         (ks + 1) * 32 + bcolb)));
            }
#pragma unroll
            for (int mi = 0; mi < 4; mi++)
#pragma unroll
                for (int ni = 0; ni < 2; ni++) {
                    mma_h(acc[mi][2 * ni], &af[cur][mi * 4], &bf[cur][ni * 4]);
                    mma_h(acc[mi][2 * ni + 1], &af[cur][mi * 4], &bf[cur][ni * 4 + 2]);
                }
        }
    }
}

// ===========================================================================
// GEMM1: expsc = fp16(exp(H/32 @ K^T)); deterministic row-sum partials
// ===========================================================================
__global__ void __launch_bounds__(TPBX, 2)
gemm1_h(const __half* __restrict__ A, const __half* __restrict__ B,
        __half* __restrict__ Cb, float* __restrict__ part) {
    extern __shared__ __align__(1024) char smem[];
    uint32_t sb = smem_u32(smem);
    int tid = threadIdx.x;
    int wid = tid >> 5, lane = tid & 31;
    int wm = wid >> 2, wn = wid & 3;        // 2x4 warp grid, warp = 64m x 32n
    int rowBase = blockIdx.y * BMX;
    int colBase = blockIdx.x * BNX;

    uint32_t acc[4][4][2];
#pragma unroll
    for (int i = 0; i < 4; i++)
#pragma unroll
        for (int j = 0; j < 4; j++) { acc[i][j][0] = 0u; acc[i][j][1] = 0u; }

    int arow = wm * 64 + (lane & 15);
    int acolb = (lane >> 4) << 4;
    int brow = wn * 32 + ((lane >> 4) << 3) + (lane & 7);
    int bcolb = ((lane >> 3) & 1) << 4;

    gemm_mainloop(A, B, DDIM, rowBase, colBase, DDIM / BKX, sb, tid,
                  arow, acolb, brow, bcolb, acc);

    int mrow = rowBase + wm * 64 + (lane >> 2);
    int ncol = colBase + wn * 32 + 2 * (lane & 3);

#pragma unroll
    for (int mi = 0; mi < 4; mi++) {
        int m0 = mrow + mi * 16;
        float s0 = 0.f, s1 = 0.f;
#pragma unroll
        for (int nj = 0; nj < 4; nj++) {
            int n = ncol + nj * 8;
            float2 r0 = __half22float2(*reinterpret_cast<__half2*>(&acc[mi][nj][0]));
            float2 r1 = __half22float2(*reinterpret_cast<__half2*>(&acc[mi][nj][1]));
            float e00 = __expf(r0.x);
            float e01 = __expf(r0.y);
            float e10 = __expf(r1.x);
            float e11 = __expf(r1.y);
            s0 += e00 + e01;
            s1 += e10 + e11;
            *reinterpret_cast<__half2*>(Cb + (size_t)m0 * MCOLS + n) =
                __floats2half2_rn(e00, e01);
            *reinterpret_cast<__half2*>(Cb + (size_t)(m0 + 8) * MCOLS + n) =
                __floats2half2_rn(e10, e11);
        }
        // fixed-order lane reduce (4 lanes share each row)
        s0 += __shfl_xor_sync(0xffffffffu, s0, 1);
        s0 += __shfl_xor_sync(0xffffffffu, s0, 2);
        s1 += __shfl_xor_sync(0xffffffffu, s1, 1);
        s1 += __shfl_xor_sync(0xffffffffu, s1, 2);
        if ((lane & 3) == 0) {
            int slot = blockIdx.x * 4 + wn;       // 32 coltiles x 4 warps = 128
            part[(size_t)m0 * 128 + slot]       = s0;
            part[(size_t)(m0 + 8) * 128 + slot] = s1;
        }
    }
}

// ===========================================================================
// GEMM2: out = (colsum(V) + (e @ Vt)/256) / z
// ===========================================================================
__global__ void __launch_bounds__(TPBX, 2)
gemm2_h(const __half* __restrict__ A, const __half* __restrict__ B,
        float* __restrict__ C,
        const float* __restrict__ ScolPart, const float* __restrict__ Zrow) {
    extern __shared__ __align__(1024) char smem[];
    uint32_t sb = smem_u32(smem);
    int tid = threadIdx.x;
    int wid = tid >> 5, lane = tid & 31;
    int wm = wid >> 2, wn = wid & 3;        // 2x4 warp grid, warp = 64m x 32n
    int rowBase = blockIdx.y * BMX;
    int colBase = blockIdx.x * BNX;

    uint32_t acc[4][4][2];
#pragma unroll
    for (int i = 0; i < 4; i++)
#pragma unroll
        for (int j = 0; j < 4; j++) { acc[i][j][0] = 0u; acc[i][j][1] = 0u; }

    int arow = wm * 64 + (lane & 15);
    int acolb = (lane >> 4) << 4;
    int brow = wn * 32 + ((lane >> 4) << 3) + (lane & 7);
    int bcolb = ((lane >> 3) & 1) << 4;

    gemm_mainloop(A, B, MCOLS, rowBase, colBase, MCOLS / BKX, sb, tid,
                  arow, acolb, brow, bcolb, acc);

    // Scol reduction into smem (safe: all cp.async drained)
    cp_wait<0>();
    __syncthreads();
    float* sS = reinterpret_cast<float*>(smem);
    if (tid < BNX) {
        float s0 = 0.f, s1 = 0.f, s2 = 0.f, s3 = 0.f;
        const float* p = ScolPart + colBase + tid;
#pragma unroll
        for (int i = 0; i < 128; i += 4) {
            s0 += p[(size_t)i * DDIM];
            s1 += p[(size_t)(i + 1) * DDIM];
            s2 += p[(size_t)(i + 2) * DDIM];
            s3 += p[(size_t)(i + 3) * DDIM];
        }
        sS[tid] = (s0 + s1) + (s2 + s3);
    }
    __syncthreads();

    const float invE = 1.0f / E_SCALE;
    int mrow = rowBase + wm * 64 + (lane >> 2);
    int ncol = colBase + wn * 32 + 2 * (lane & 3);
#pragma unroll
    for (int mi = 0; mi < 4; mi++) {
        int m0 = mrow + mi * 16;
        float rz0 = 1.0f / Zrow[m0];
        float rz1 = 1.0f / Zrow[m0 + 8];
#pragma unroll
        for (int nj = 0; nj < 4; nj++) {
            int n = ncol + nj * 8;
            float s0 = sS[n - colBase], s1 = sS[n - colBase + 1];
            float2 r0 = __half22float2(*reinterpret_cast<__half2*>(&acc[mi][nj][0]));
            float2 r1 = __half22float2(*reinterpret_cast<__half2*>(&acc[mi][nj][1]));
            float2 v0, v1;
            v0.x = (s0 + r0.x * invE) * rz0;
            v0.y = (s1 + r0.y * invE) * rz0;
            v1.x = (s0 + r1.x * invE) * rz1;
            v1.y = (s1 + r1.y * invE) * rz1;
            *reinterpret_cast<float2*>(C + (size_t)m0 * DDIM + n) = v0;
            *reinterpret_cast<float2*>(C + (size_t)(m0 + 8) * DDIM + n) = v1;
        }
    }
}

// ---------------------------------------------------------------------------
// Elementwise / reduction kernels
// ---------------------------------------------------------------------------
// fp32 -> fp16 with scale; each thread: 2 x float4 loads, 1 x 16B store
__global__ void conv_f2h(const float* __restrict__ src, __half* __restrict__ dst,
                         float scale) {
    int i = blockIdx.x * blockDim.x + threadIdx.x;   // 8-element group id
    const float4* s4 = reinterpret_cast<const float4*>(src) + 2 * (size_t)i;
    float4 a = s4[0], b = s4[1];
    __half2 h[4];
    h[0] = __floats2half2_rn(a.x * scale, a.y * scale);
    h[1] = __floats2half2_rn(a.z * scale, a.w * scale);
    h[2] = __floats2half2_rn(b.x * scale, b.y * scale);
    h[3] = __floats2half2_rn(b.z * scale, b.w * scale);
    reinterpret_cast<uint4*>(dst)[i] = *reinterpret_cast<uint4*>(h);
}

// V^T (fp16) + per-row-tile column partial sums (single pass over V)
__global__ void transposeV(const float* __restrict__ V, __half* __restrict__ Vt,
                           float* __restrict__ partc) {
    __shared__ float tile[32][33];
    __shared__ float red[8][32];
    int d0 = blockIdx.x * 32, m0 = blockIdx.y * 32;
    int tx = threadIdx.x, ty = threadIdx.y;  // 32 x 8
#pragma unroll
    for (int j = 0; j < 32; j += 8)
        tile[ty + j][tx] = V[(size_t)(m0 + ty + j) * DDIM + d0 + tx];
    __syncthreads();
    // fp16 transpose: thread handles (d_local = ty*4 + tx/8, m = 4*(tx&7)..+3)
    {
        int dl = ty * 4 + (tx >> 3);
        int ml = 4 * (tx & 7);
        __half2 w0 = __floats2half2_rn(tile[ml][dl], tile[ml + 1][dl]);
        __half2 w1 = __floats2half2_rn(tile[ml + 2][dl], tile[ml + 3][dl]);
        __half2* dst = reinterpret_cast<__half2*>(Vt + (size_t)(d0 + dl) * MCOLS + m0 + ml);
        dst[0] = w0;
        dst[1] = w1;
    }
    // column partials: sum over the 32 m-rows for each d = tx
    float s = (tile[ty * 4 + 0][tx] + tile[ty * 4 + 1][tx]) +
              (tile[ty * 4 + 2][tx] + tile[ty * 4 + 3][tx]);
    red[ty][tx] = s;
    __syncthreads();
    if (ty == 0) {
        float t = 0.f;
#pragma unroll
        for (int i = 0; i < 8; i++) t += red[i][tx];
        partc[(size_t)blockIdx.y * DDIM + d0 + tx] = t;
    }
}

static __device__ __forceinline__ float warp_red_sum(float v) {
#pragma unroll
    for (int o = 16; o > 0; o >>= 1) v += __shfl_xor_sync(0xffffffffu, v, o);
    return v;
}

// fast expm1 for small non-negative x: cubic Taylor, guard to expm1f
static __device__ __forceinline__ float expm1_fast(float x) {
    float p = x * (1.0f + x * (0.5f + x * 0.16666667f));
    return (x > 0.0625f) ? expm1f(x) : p;
}

// build_e with fused row-sum reduction (reads 128 partials in-block)
__global__ void build_e(const __half* __restrict__ expsc,
                        const float* __restrict__ mask,
                        const float* __restrict__ part,
                        __half* __restrict__ e, float* __restrict__ zrow) {
    __shared__ float red[8];
    __shared__ float srsum;
    int n = blockIdx.x, t = threadIdx.x;
    int wid = t >> 5, lid = t & 31;
    // warp 0: reduce the 128 row partials (fixed order)
    if (wid == 0) {
        const float* p = part + (size_t)n * 128;
        float s = (p[lid] + p[lid + 32]) + (p[lid + 64] + p[lid + 96]);
        s = warp_red_sum(s);
        if (lid == 0) srsum = s;
    }
    const __half2* srow = reinterpret_cast<const __half2*>(expsc + (size_t)n * MCOLS);
    const float4* mrow = reinterpret_cast<const float4*>(mask + (size_t)n * MCOLS);
    __half2* erow = reinterpret_cast<__half2*>(e + (size_t)n * MCOLS);
    __syncthreads();
    float inv = 1.0f / srsum;
    float z = 0.f;
#pragma unroll
    for (int i = 0; i < 4; i++) {
        int idx = t + i * 256;
        float4 m = mrow[idx];
        __half2 p0 = srow[2 * idx];
        __half2 p1 = srow[2 * idx + 1];
        float e0 = expm1_fast(__low2float(p0)  * inv * m.x);
        float e1 = expm1_fast(__high2float(p0) * inv * m.y);
        float e2 = expm1_fast(__low2float(p1)  * inv * m.z);
        float e3 = expm1_fast(__high2float(p1) * inv * m.w);
        z += (e0 + e1) + (e2 + e3);
        erow[2 * idx]     = __floats2half2_rn(e0 * E_SCALE, e1 * E_SCALE);
        erow[2 * idx + 1] = __floats2half2_rn(e2 * E_SCALE, e3 * E_SCALE);
    }
    z = warp_red_sum(z);
    if (lid == 0) red[wid] = z;
    __syncthreads();
    if (t == 0) {
        float acc = 0.f;
#pragma unroll
        for (int i = 0; i < 8; i++) acc += red[i];
        zrow[n] = (float)MCOLS + acc;
    }
}

// ---------------------------------------------------------------------------
// Launch
// ---------------------------------------------------------------------------
extern "C" void kernel_launch(void* const* d_in, const int* in_sizes, int n_in,
                              void* d_out, int out_size) {
    const float* H   = (const float*)d_in[0];
    const float* K   = (const float*)d_in[1];
    const float* V   = (const float*)d_in[2];
    const float* Msk = (const float*)d_in[3];
    float* out = (float*)d_out;

    void *hh, *kh, *vt, *es, *ee, *zz, *part, *partc;
    cudaGetSymbolAddress(&hh, g_Hh);
    cudaGetSymbolAddress(&kh, g_Kh);
    cudaGetSymbolAddress(&vt, g_Vt);
    cudaGetSymbolAddress(&es, g_expsc);
    cudaGetSymbolAddress(&ee, g_e);
    cudaGetSymbolAddress(&zz, g_z);
    cudaGetSymbolAddress(&part, g_part);
    cudaGetSymbolAddress(&partc, g_partc);

    cudaFuncSetAttribute(gemm1_h, cudaFuncAttributeMaxDynamicSharedMemorySize,
                         SMEMX_BYTES);
    cudaFuncSetAttribute(gemm2_h, cudaFuncAttributeMaxDynamicSharedMemorySize,
                         SMEMX_BYTES);

    // Launch order keeps gemm1_h at slot 4 (the ncu-profiled slot).
    conv_f2h<<<(NROWS * DDIM / 8) / 256, 256>>>(H, (__half*)hh, 1.0f / 32.0f);  // 1
    conv_f2h<<<(MCOLS * DDIM / 8) / 256, 256>>>(K, (__half*)kh, 1.0f);          // 2
    transposeV<<<dim3(DDIM / 32, MCOLS / 32), dim3(32, 8)>>>(V, (__half*)vt,
                                                             (float*)partc);    // 3

    // Stage 1: expsc = fp16(exp(H/32 @ K^T)) + row-sum partials (fused epilogue)
    gemm1_h<<<dim3(MCOLS / BNX, NROWS / BMX), TPBX, SMEMX_BYTES>>>(
        (const __half*)hh, (const __half*)kh, (__half*)es, (float*)part);       // 4

    // Stage 2: e = fp16(expm1(softmax1 * mask) * 256); z = M + sum(e)
    build_e<<<NROWS, 256>>>((const __half*)es, Msk, (const float*)part,
                            (__half*)ee, (float*)zz);                           // 5

    // Stage 3: out = (colsum(V) + (e @ V)/256) / z   (fp16-acc tensor cores)
    gemm2_h<<<dim3(DDIM / BNX, NROWS / BMX), TPBX, SMEMX_BYTES>>>(
        (const __half*)ee, (const __half*)vt, out,
        (const float*)partc, (const float*)zz);                                 // 6
}

// round 15
// speedup vs baseline: 1.0349x; 1.0332x over previous
#include <cuda_runtime.h>
#include <cuda_fp16.h>
#include <cstdint>
#include <cstddef>

// Problem dims (fixed)
#define NROWS 4096
#define MCOLS 4096
#define DDIM  1024
#define E_SCALE 256.0f

// ---------------------------------------------------------------------------
// Scratch (__device__ globals — allocation-free contract)
// ---------------------------------------------------------------------------
__device__ __half g_Hh[(size_t)NROWS * DDIM];     // H * (1/32) in fp16
__device__ __half g_Kh[(size_t)MCOLS * DDIM];     // K in fp16
__device__ __half g_Vt[(size_t)DDIM * MCOLS];     // V^T in fp16 (K-major)
__device__ __half g_expsc[(size_t)NROWS * MCOLS]; // exp(scores) fp16
__device__ __half g_e[(size_t)NROWS * MCOLS];     // expm1(p*mask)*256 fp16
__device__ float g_z[NROWS];
__device__ float g_part[(size_t)NROWS * 128];  // GEMM1 row-sum partials [row][slot]
__device__ float g_partc[128 * DDIM];          // V colsum partials (128 row-tiles)

static __device__ __forceinline__ uint32_t smem_u32(const void* p) {
    uint32_t a;
    asm("{ .reg .u64 t; cvta.to.shared.u64 t, %1; cvt.u32.u64 %0, t; }"
        : "=r"(a) : "l"(p));
    return a;
}

static __device__ __forceinline__ uint32_t sw128(uint32_t off) {
    return off ^ ((off >> 3) & 0x70);
}

static __device__ __forceinline__ void cp16(uint32_t saddr, const void* gptr) {
    asm volatile("cp.async.cg.shared.global [%0], [%1], 16;"
                 :: "r"(saddr), "l"(gptr));
}

static __device__ __forceinline__ void cp_commit() {
    asm volatile("cp.async.commit_group;");
}

template <int N>
static __device__ __forceinline__ void cp_wait() {
    asm volatile("cp.async.wait_group %0;" :: "n"(N));
}

static __device__ __forceinline__ void ldmatrix_x4(uint32_t* r, uint32_t saddr) {
    asm volatile("ldmatrix.sync.aligned.m8n8.x4.shared.b16 {%0,%1,%2,%3}, [%4];"
                 : "=r"(r[0]), "=r"(r[1]), "=r"(r[2]), "=r"(r[3]) : "r"(saddr));
}

// fp16-accumulate HMMA (numerics validated: rel_err 8.7e-7 end-to-end)
static __device__ __forceinline__ void mma_h(uint32_t* d, const uint32_t* a,
                                             const uint32_t* b) {
    asm volatile(
        "mma.sync.aligned.m16n8k16.row.col.f16.f16.f16.f16 "
        "{%0,%1}, {%2,%3,%4,%5}, {%6,%7}, {%0,%1};"
        : "+r"(d[0]), "+r"(d[1])
        : "r"(a[0]), "r"(a[1]), "r"(a[2]), "r"(a[3]), "r"(b[0]), "r"(b[1]));
}

// ===========================================================================
// GEMM1 (R14 best-measured, 97.2us): 128x128 CTA tile, BK=64, 256 thr,
//   8 warps (2x4), warp tile 64x32, ST=3, fragment double-buffering.
// ===========================================================================
#define BMX 128
#define BNX 128
#define BKX 64
#define TPBX 256
#define STX 3
#define AX_BYTES 16384             // 128 x 64 fp16
#define STGX_BYTES (2 * AX_BYTES)
#define SMEMX_BYTES (STX * STGX_BYTES)   // 96 KB

static __device__ __forceinline__ void issue_stageX(
    const __half* __restrict__ A, const __half* __restrict__ B,
    int lda, int rowBase, int colBase, int k0, uint32_t sbase, int tid) {
    uint32_t sA = sbase;
    uint32_t sB = sbase + AX_BYTES;
#pragma unroll
    for (int i = 0; i < 4; i++) {      // A, B: 1024 x 16B chunks each
        int l = tid + i * TPBX;
        int r = l >> 3, c = l & 7;
        uint32_t off = sw128((uint32_t)(r * 128 + c * 16));
        cp16(sA + off, A + (size_t)(rowBase + r) * lda + k0 + c * 8);
        cp16(sB + off, B + (size_t)(colBase + r) * lda + k0 + c * 8);
    }
}

static __device__ __forceinline__ void gemm_mainloop(
    const __half* __restrict__ A, const __half* __restrict__ B, int lda,
    int rowBase, int colBase, int nIter, uint32_t sb, int tid,
    int arow, int acolb, int brow, int bcolb, uint32_t acc[4][4][2]) {

#pragma unroll
    for (int s = 0; s < STX - 1; s++) {
        issue_stageX(A, B, lda, rowBase, colBase, s * BKX,
                     sb + s * STGX_BYTES, tid);
        cp_commit();
    }

    for (int it = 0; it < nIter; ++it) {
        cp_wait<1>();
        __syncthreads();
        if (it + STX - 1 < nIter) {
            issue_stageX(A, B, lda, rowBase, colBase, (it + STX - 1) * BKX,
                         sb + ((it + STX - 1) % STX) * STGX_BYTES, tid);
            cp_commit();
        }

        uint32_t baseA = sb + (it % STX) * STGX_BYTES;
        uint32_t baseB = baseA + AX_BYTES;

        uint32_t af[2][16], bf[2][8];
#pragma unroll
        for (int mi = 0; mi < 4; mi++)
            ldmatrix_x4(&af[0][mi * 4],
                        baseA + sw128((uint32_t)((arow + mi * 16) * 128 + acolb)));
#pragma unroll
        for (int ni = 0; ni < 2; ni++)
            ldmatrix_x4(&bf[0][ni * 4],
                        baseB + sw128((uint32_t)((brow + ni * 16) * 128 + bcolb)));

#pragma unroll
        for (int ks = 0; ks < 4; ks++) {
            int cur = ks & 1, nxt = cur ^ 1;
            if (ks < 3) {
#pragma unroll
                for (int mi = 0; mi < 4; mi++)
                    ldmatrix_x4(&af[nxt][mi * 4],
                                baseA + sw128((uint32_t)((arow + mi * 16) * 128 +
                                                         (ks + 1) * 32 + acolb)));
#pragma unroll
                for (int ni = 0; ni < 2; ni++)
                    ldmatrix_x4(&bf[nxt][ni * 4],
                                baseB + sw128((uint32_t)((brow + ni * 16) * 128 +
                                                         (ks + 1) * 32 + bcolb)));
            }
#pragma unroll
            for (int mi = 0; mi < 4; mi++)
#pragma unroll
                for (int ni = 0; ni < 2; ni++) {
                    mma_h(acc[mi][2 * ni], &af[cur][mi * 4], &bf[cur][ni * 4]);
                    mma_h(acc[mi][2 * ni + 1], &af[cur][mi * 4], &bf[cur][ni * 4 + 2]);
                }
        }
    }
}

__global__ void __launch_bounds__(TPBX, 2)
gemm1_h(const __half* __restrict__ A, const __half* __restrict__ B,
        __half* __restrict__ Cb, float* __restrict__ part) {
    extern __shared__ __align__(1024) char smem[];
    uint32_t sb = smem_u32(smem);
    int tid = threadIdx.x;
    int wid = tid >> 5, lane = tid & 31;
    int wm = wid >> 2, wn = wid & 3;        // 2x4 warp grid, warp = 64m x 32n
    int rowBase = blockIdx.y * BMX;
    int colBase = blockIdx.x * BNX;

    uint32_t acc[4][4][2];
#pragma unroll
    for (int i = 0; i < 4; i++)
#pragma unroll
        for (int j = 0; j < 4; j++) { acc[i][j][0] = 0u; acc[i][j][1] = 0u; }

    int arow = wm * 64 + (lane & 15);
    int acolb = (lane >> 4) << 4;
    int brow = wn * 32 + ((lane >> 4) << 3) + (lane & 7);
    int bcolb = ((lane >> 3) & 1) << 4;

    gemm_mainloop(A, B, DDIM, rowBase, colBase, DDIM / BKX, sb, tid,
                  arow, acolb, brow, bcolb, acc);

    int mrow = rowBase + wm * 64 + (lane >> 2);
    int ncol = colBase + wn * 32 + 2 * (lane & 3);

#pragma unroll
    for (int mi = 0; mi < 4; mi++) {
        int m0 = mrow + mi * 16;
        float s0 = 0.f, s1 = 0.f;
#pragma unroll
        for (int nj = 0; nj < 4; nj++) {
            int n = ncol + nj * 8;
            float2 r0 = __half22float2(*reinterpret_cast<__half2*>(&acc[mi][nj][0]));
            float2 r1 = __half22float2(*reinterpret_cast<__half2*>(&acc[mi][nj][1]));
            float e00 = __expf(r0.x);
            float e01 = __expf(r0.y);
            float e10 = __expf(r1.x);
            float e11 = __expf(r1.y);
            s0 += e00 + e01;
            s1 += e10 + e11;
            *reinterpret_cast<__half2*>(Cb + (size_t)m0 * MCOLS + n) =
                __floats2half2_rn(e00, e01);
            *reinterpret_cast<__half2*>(Cb + (size_t)(m0 + 8) * MCOLS + n) =
                __floats2half2_rn(e10, e11);
        }
        s0 += __shfl_xor_sync(0xffffffffu, s0, 1);
        s0 += __shfl_xor_sync(0xffffffffu, s0, 2);
        s1 += __shfl_xor_sync(0xffffffffu, s1, 1);
        s1 += __shfl_xor_sync(0xffffffffu, s1, 2);
        if ((lane & 3) == 0) {
            int slot = blockIdx.x * 4 + wn;       // 32 coltiles x 4 warps = 128
            part[(size_t)m0 * 128 + slot]       = s0;
            part[(size_t)(m0 + 8) * 128 + slot] = s1;
        }
    }
}

// ===========================================================================
// GEMM2 (R10 measured-best geometry): 128(M) x 256(N) CTA tile, BK=64,
//   256 thr (8 warps 2x4, warp tile 64x64), ST=3 (144 KB, 1 CTA/SM).
//   out = (Scol[col] + acc/256) / Zrow[row]
// ===========================================================================
#define BM2 128
#define BN2 256
#define BK2 64
#define TPB2 256
#define ST2 3
#define A2_BYTES 16384             // 128 x 64 fp16
#define B2_BYTES 32768             // 256 x 64 fp16
#define STG2_BYTES (A2_BYTES + B2_BYTES)
#define SMEM2_BYTES (ST2 * STG2_BYTES)

static __device__ __forceinline__ void issue_stage2(
    const __half* __restrict__ A, const __half* __restrict__ B,
    int rowBase, int colBase, int k0, uint32_t sbase, int tid) {
    uint32_t sA = sbase;
    uint32_t sB = sbase + A2_BYTES;
#pragma unroll
    for (int i = 0; i < 4; i++) {      // A: 1024 chunks
        int l = tid + i * TPB2;
        int r = l >> 3, c = l & 7;
        uint32_t off = sw128((uint32_t)(r * 128 + c * 16));
        cp16(sA + off, A + (size_t)(rowBase + r) * MCOLS + k0 + c * 8);
    }
#pragma unroll
    for (int i = 0; i < 8; i++) {      // B: 2048 chunks
        int l = tid + i * TPB2;
        int r = l >> 3, c = l & 7;
        uint32_t off = sw128((uint32_t)(r * 128 + c * 16));
        cp16(sB + off, B + (size_t)(colBase + r) * MCOLS + k0 + c * 8);
    }
}

__global__ void __launch_bounds__(TPB2, 1)
gemm2_h(const __half* __restrict__ A, const __half* __restrict__ B,
        float* __restrict__ C,
        const float* __restrict__ ScolPart, const float* __restrict__ Zrow) {
    extern __shared__ __align__(1024) char smem[];
    uint32_t sb = smem_u32(smem);
    int tid = threadIdx.x;
    int wid = tid >> 5, lane = tid & 31;
    int wm = wid >> 2, wn = wid & 3;        // 2x4 warp grid, warp = 64m x 64n
    int rowBase = blockIdx.y * BM2;
    int colBase = blockIdx.x * BN2;
    const int nIter = MCOLS / BK2;          // 64

#pragma unroll
    for (int s = 0; s < ST2 - 1; s++) {
        issue_stage2(A, B, rowBase, colBase, s * BK2, sb + s * STG2_BYTES, tid);
        cp_commit();
    }

    uint32_t acc[4][8][2];
#pragma unroll
    for (int i = 0; i < 4; i++)
#pragma unroll
        for (int j = 0; j < 8; j++) { acc[i][j][0] = 0u; acc[i][j][1] = 0u; }

    int arow = wm * 64 + (lane & 15);
    int acolb = (lane >> 4) << 4;
    int brow = wn * 64 + ((lane >> 4) << 3) + (lane & 7);
    int bcolb = ((lane >> 3) & 1) << 4;

    int stage = 0;
    for (int it = 0; it < nIter; ++it) {
        cp_wait<ST2 - 2>();
        __syncthreads();
        uint32_t baseA = sb + stage * STG2_BYTES;
        uint32_t baseB = baseA + A2_BYTES;

#pragma unroll
        for (int ks = 0; ks < 4; ks++) {
            uint32_t af[4][4];
#pragma unroll
            for (int mi = 0; mi < 4; mi++) {
                uint32_t off = sw128((uint32_t)((arow + mi * 16) * 128 + ks * 32 + acolb));
                ldmatrix_x4(af[mi], baseA + off);
            }
            uint32_t bf[4][4];
#pragma unroll
            for (int ni = 0; ni < 4; ni++) {
                uint32_t off = sw128((uint32_t)((brow + ni * 16) * 128 + ks * 32 + bcolb));
                ldmatrix_x4(bf[ni], baseB + off);
            }
#pragma unroll
            for (int mi = 0; mi < 4; mi++)
#pragma unroll
                for (int ni = 0; ni < 4; ni++) {
                    mma_h(acc[mi][2 * ni], af[mi], &bf[ni][0]);
                    mma_h(acc[mi][2 * ni + 1], af[mi], &bf[ni][2]);
                }
        }

        int nxt = it + ST2 - 1;
        if (nxt < nIter) {
            issue_stage2(A, B, rowBase, colBase, nxt * BK2,
                         sb + ((nxt % ST2) * STG2_BYTES), tid);
        }
        cp_commit();
        stage = (stage + 1 == ST2) ? 0 : stage + 1;
    }

    // Scol reduction into smem (safe: all cp.async drained)
    cp_wait<0>();
    __syncthreads();
    float* sS = reinterpret_cast<float*>(smem);
    {
        float s0 = 0.f, s1 = 0.f, s2 = 0.f, s3 = 0.f;
        const float* p = ScolPart + colBase + tid;
#pragma unroll
        for (int i = 0; i < 128; i += 4) {
            s0 += p[(size_t)i * DDIM];
            s1 += p[(size_t)(i + 1) * DDIM];
            s2 += p[(size_t)(i + 2) * DDIM];
            s3 += p[(size_t)(i + 3) * DDIM];
        }
        sS[tid] = (s0 + s1) + (s2 + s3);
    }
    __syncthreads();

    const float invE = 1.0f / E_SCALE;
    int mrow = rowBase + wm * 64 + (lane >> 2);
    int ncol = colBase + wn * 64 + 2 * (lane & 3);
#pragma unroll
    for (int mi = 0; mi < 4; mi++) {
        int m0 = mrow + mi * 16;
        float rz0 = 1.0f / Zrow[m0];
        float rz1 = 1.0f / Zrow[m0 + 8];
#pragma unroll
        for (int nj = 0; nj < 8; nj++) {
            int n = ncol + nj * 8;
            float s0 = sS[n - colBase], s1 = sS[n - colBase + 1];
            float2 r0 = __half22float2(*reinterpret_cast<__half2*>(&acc[mi][nj][0]));
            float2 r1 = __half22float2(*reinterpret_cast<__half2*>(&acc[mi][nj][1]));
            float2 v0, v1;
            v0.x = (s0 + r0.x * invE) * rz0;
            v0.y = (s1 + r0.y * invE) * rz0;
            v1.x = (s0 + r1.x * invE) * rz1;
            v1.y = (s1 + r1.y * invE) * rz1;
            *reinterpret_cast<float2*>(C + (size_t)m0 * DDIM + n) = v0;
            *reinterpret_cast<float2*>(C + (size_t)(m0 + 8) * DDIM + n) = v1;
        }
    }
}

// ---------------------------------------------------------------------------
// Elementwise / reduction kernels
// ---------------------------------------------------------------------------
__global__ void conv_f2h(const float* __restrict__ src, __half* __restrict__ dst,
                         float scale) {
    int i = blockIdx.x * blockDim.x + threadIdx.x;   // 8-element group id
    const float4* s4 = reinterpret_cast<const float4*>(src) + 2 * (size_t)i;
    float4 a = s4[0], b = s4[1];
    __half2 h[4];
    h[0] = __floats2half2_rn(a.x * scale, a.y * scale);
    h[1] = __floats2half2_rn(a.z * scale, a.w * scale);
    h[2] = __floats2half2_rn(b.x * scale, b.y * scale);
    h[3] = __floats2half2_rn(b.z * scale, b.w * scale);
    reinterpret_cast<uint4*>(dst)[i] = *reinterpret_cast<uint4*>(h);
}

// V^T (fp16) + per-row-tile column partial sums (single pass over V)
__global__ void transposeV(const float* __restrict__ V, __half* __restrict__ Vt,
                           float* __restrict__ partc) {
    __shared__ float tile[32][33];
    __shared__ float red[8][32];
    int d0 = blockIdx.x * 32, m0 = blockIdx.y * 32;
    int tx = threadIdx.x, ty = threadIdx.y;  // 32 x 8
#pragma unroll
    for (int j = 0; j < 32; j += 8)
        tile[ty + j][tx] = V[(size_t)(m0 + ty + j) * DDIM + d0 + tx];
    __syncthreads();
    {
        int dl = ty * 4 + (tx >> 3);
        int ml = 4 * (tx & 7);
        __half2 w0 = __floats2half2_rn(tile[ml][dl], tile[ml + 1][dl]);
        __half2 w1 = __floats2half2_rn(tile[ml + 2][dl], tile[ml + 3][dl]);
        __half2* dst = reinterpret_cast<__half2*>(Vt + (size_t)(d0 + dl) * MCOLS + m0 + ml);
        dst[0] = w0;
        dst[1] = w1;
    }
    float s = (tile[ty * 4 + 0][tx] + tile[ty * 4 + 1][tx]) +
              (tile[ty * 4 + 2][tx] + tile[ty * 4 + 3][tx]);
    red[ty][tx] = s;
    __syncthreads();
    if (ty == 0) {
        float t = 0.f;
#pragma unroll
        for (int i = 0; i < 8; i++) t += red[i][tx];
        partc[(size_t)blockIdx.y * DDIM + d0 + tx] = t;
    }
}

static __device__ __forceinline__ float warp_red_sum(float v) {
#pragma unroll
    for (int o = 16; o > 0; o >>= 1) v += __shfl_xor_sync(0xffffffffu, v, o);
    return v;
}

// fast expm1 for small non-negative x: cubic Taylor, guard to expm1f
static __device__ __forceinline__ float expm1_fast(float x) {
    float p = x * (1.0f + x * (0.5f + x * 0.16666667f));
    return (x > 0.0625f) ? expm1f(x) : p;
}

// build_e with fused row-sum reduction (reads 128 partials in-block)
__global__ void build_e(const __half* __restrict__ expsc,
                        const float* __restrict__ mask,
                        const float* __restrict__ part,
                        __half* __restrict__ e, float* __restrict__ zrow) {
    __shared__ float red[8];
    __shared__ float srsum;
    int n = blockIdx.x, t = threadIdx.x;
    int wid = t >> 5, lid = t & 31;
    if (wid == 0) {
        const float* p = part + (size_t)n * 128;
        float s = (p[lid] + p[lid + 32]) + (p[lid + 64] + p[lid + 96]);
        s = warp_red_sum(s);
        if (lid == 0) srsum = s;
    }
    const __half2* srow = reinterpret_cast<const __half2*>(expsc + (size_t)n * MCOLS);
    const float4* mrow = reinterpret_cast<const float4*>(mask + (size_t)n * MCOLS);
    __half2* erow = reinterpret_cast<__half2*>(e + (size_t)n * MCOLS);
    __syncthreads();
    float inv = 1.0f / srsum;
    float z = 0.f;
#pragma unroll
    for (int i = 0; i < 4; i++) {
        int idx = t + i * 256;
        float4 m = mrow[idx];
        __half2 p0 = srow[2 * idx];
        __half2 p1 = srow[2 * idx + 1];
        float e0 = expm1_fast(__low2float(p0)  * inv * m.x);
        float e1 = expm1_fast(__high2float(p0) * inv * m.y);
        float e2 = expm1_fast(__low2float(p1)  * inv * m.z);
        float e3 = expm1_fast(__high2float(p1) * inv * m.w);
        z += (e0 + e1) + (e2 + e3);
        erow[2 * idx]     = __floats2half2_rn(e0 * E_SCALE, e1 * E_SCALE);
        erow[2 * idx + 1] = __floats2half2_rn(e2 * E_SCALE, e3 * E_SCALE);
    }
    z = warp_red_sum(z);
    if (lid == 0) red[wid] = z;
    __syncthreads();
    if (t == 0) {
        float acc = 0.f;
#pragma unroll
        for (int i = 0; i < 8; i++) acc += red[i];
        zrow[n] = (float)MCOLS + acc;
    }
}

// ---------------------------------------------------------------------------
// Launch — transposeV forked onto a side stream, overlapping conv+gemm1.
// Streams/events created once on the first (uncaptured correctness) call;
// the captured graph contains identical work every call.
// ---------------------------------------------------------------------------
extern "C" void kernel_launch(void* const* d_in, const int* in_sizes, int n_in,
                              void* d_out, int out_size) {
    const float* H   = (const float*)d_in[0];
    const float* K   = (const float*)d_in[1];
    const float* V   = (const float*)d_in[2];
    const float* Msk = (const float*)d_in[3];
    float* out = (float*)d_out;

    void *hh, *kh, *vt, *es, *ee, *zz, *part, *partc;
    cudaGetSymbolAddress(&hh, g_Hh);
    cudaGetSymbolAddress(&kh, g_Kh);
    cudaGetSymbolAddress(&vt, g_Vt);
    cudaGetSymbolAddress(&es, g_expsc);
    cudaGetSymbolAddress(&ee, g_e);
    cudaGetSymbolAddress(&zz, g_z);
    cudaGetSymbolAddress(&part, g_part);
    cudaGetSymbolAddress(&partc, g_partc);

    cudaFuncSetAttribute(gemm1_h, cudaFuncAttributeMaxDynamicSharedMemorySize,
                         SMEMX_BYTES);
    cudaFuncSetAttribute(gemm2_h, cudaFuncAttributeMaxDynamicSharedMemorySize,
                         SMEM2_BYTES);

    static cudaStream_t s_side = nullptr;
    static cudaEvent_t ev_fork = nullptr, ev_side = nullptr;
    if (s_side == nullptr) {
        cudaStreamCreateWithFlags(&s_side, cudaStreamNonBlocking);
        cudaEventCreateWithFlags(&ev_fork, cudaEventDisableTiming);
        cudaEventCreateWithFlags(&ev_side, cudaEventDisableTiming);
    }

    // Fork: transposeV (independent of gemm1) runs on the side stream.
    cudaEventRecord(ev_fork, 0);
    cudaStreamWaitEvent(s_side, ev_fork, 0);
    transposeV<<<dim3(DDIM / 32, MCOLS / 32), dim3(32, 8), 0, s_side>>>(
        V, (__half*)vt, (float*)partc);                                         // 1
    cudaEventRecord(ev_side, s_side);

    // Main stream: conversions -> gemm1 -> build_e
    conv_f2h<<<(NROWS * DDIM / 8) / 256, 256>>>(H, (__half*)hh, 1.0f / 32.0f);  // 2
    conv_f2h<<<(MCOLS * DDIM / 8) / 256, 256>>>(K, (__half*)kh, 1.0f);          // 3

    gemm1_h<<<dim3(MCOLS / BNX, NROWS / BMX), TPBX, SMEMX_BYTES>>>(
        (const __half*)hh, (const __half*)kh, (__half*)es, (float*)part);       // 4

    build_e<<<NROWS, 256>>>((const __half*)es, Msk, (const float*)part,
                            (__half*)ee, (float*)zz);                           // 5

    // Join: gemm2 needs Vt + partc from the side stream.
    cudaStreamWaitEvent(0, ev_side, 0);
    gemm2_h<<<dim3(DDIM / BN2, NROWS / BM2), TPB2, SMEM2_BYTES>>>(
        (const __half*)ee, (const __half*)vt, out,
        (const float*)partc, (const float*)zz);                                 // 6
}